// round 6
// baseline (speedup 1.0000x reference)
#include <cuda_runtime.h>

#define FULL 0xFFFFFFFFu
static const int NROW = 25200;
static const int BIMG = 8;
static const int NBIN = 16384;
static const int KC   = 512;
static const int KP   = 1024;
static const int TILE = 112;               // 25200 = 225 * 112
static const int NTILE = NROW / TILE;      // 225
static const int BCAP = 1024;              // per coarse bucket capacity

// ---------------- global scratch (static __device__, no allocation) -------
__device__ int                g_bcnt[16][64];
__device__ unsigned long long g_bucket[16][64][BCAP];
__device__ float4             g_box [2][BIMG][KP];
__device__ unsigned char      g_cls [2][BIMG][KP];
__device__ unsigned char      g_keep[2][BIMG][KP];
__device__ int                g_flag[BIMG];
__device__ float              g_s[BIMG], g_n[BIMG];
__device__ int                g_cnt;

__device__ __forceinline__ float iou_rn(float4 a, float4 b) {
    float tlx = fmaxf(a.x, b.x), tly = fmaxf(a.y, b.y);
    float brx = fminf(a.z, b.z), bry = fminf(a.w, b.w);
    float w = fmaxf(__fsub_rn(brx, tlx), 0.0f);
    float h = fmaxf(__fsub_rn(bry, tly), 0.0f);
    float inter = __fmul_rn(w, h);
    float aa = __fmul_rn(__fsub_rn(a.z, a.x), __fsub_rn(a.w, a.y));
    float ab = __fmul_rn(__fsub_rn(b.z, b.x), __fsub_rn(b.w, b.y));
    float uni = __fsub_rn(__fadd_rn(aa, ab), inter);
    uni = (uni > 0.0f) ? uni : 1.0f;
    return __fdiv_rn(inter, uni);
}

__device__ __forceinline__ int binof(float conf) {
    int b = (int)(conf * 16384.0f);
    return b > NBIN - 1 ? NBIN - 1 : (b < 0 ? 0 : b);
}
__device__ __forceinline__ float conf_of(unsigned long long key) {
    return __uint_as_float((unsigned)(key >> 32) ^ 0x80000000u);
}

// ---------------- K1: tile-staged score -> bucketed candidates -------------
__global__ void __launch_bounds__(128) k_score(const float* __restrict__ clean,
                                               const float* __restrict__ patch) {
    __shared__ float sd[TILE * 85];
    int seg   = blockIdx.y;
    int which = seg >> 3, img = seg & 7;
    int tile  = blockIdx.x;
    const float* base = (which ? patch : clean)
                      + ((size_t)img * NROW + (size_t)tile * TILE) * 85;
    const float4* b4 = (const float4*)base;
    float4* s4 = (float4*)sd;
    const int NV4 = TILE * 85 / 4;                      // 2380
    #pragma unroll 5
    for (int i = threadIdx.x; i < NV4; i += 128) s4[i] = b4[i];
    __syncthreads();

    int tid = threadIdx.x;
    if (tid < TILE) {
        const float* row = sd + tid * 85;
        float obj = row[4];
        float bv = -1.0f; int bc = 5;
        #pragma unroll
        for (int c = 5; c < 85; c++) {
            float x = __fmul_rn(row[c], obj);
            if (x > bv) { bv = x; bc = c; }             // strict > keeps earliest
        }
        int r = tile * TILE + tid;
        float TH = which ? 0.001f : 0.25f;
        if (obj > TH && bv > TH) {
            unsigned u = __float_as_uint(bv) ^ 0x80000000u;
            unsigned long long key = ((unsigned long long)u << 32)
                | ((unsigned)(32767 - r) << 7) | (unsigned)(bc - 5);
            int bin = binof(bv);
            int b = bin >> 8;                            // coarse bucket
            int pos = atomicAdd(&g_bcnt[seg][b], 1);
            if (pos < BCAP) g_bucket[seg][b][pos] = key;
        }
    }
}

// ---------------- K2: threshold + gather + tie + NMS + fused loss ----------
__global__ void __launch_bounds__(1024) k_select(const float* __restrict__ clean,
                                                 const float* __restrict__ patch,
                                                 float* __restrict__ out) {
    __shared__ union {
        struct {
            unsigned long long skey[KP];
            unsigned long long tie[BCAP];
            float4 obox[KP];
            short  clslist[80 * 64];
        } sel;
        struct {
            float4 pdiv[KP];
            short  plist[80 * 128];
        } loss;
    } U;
    __shared__ unsigned char keepc[KP];
    __shared__ int   bcnt[64];
    __shared__ int   hfine[256];
    __shared__ int   ccnt[80];
    __shared__ int   wsum[32];
    __shared__ float rs[32], rn2[32];
    __shared__ int   sBstar, sKp, sAllin, sT, sNeed, sNin, sNtie;

    int seg = blockIdx.x;
    int which = seg >> 3, img = seg & 7;
    int K = which ? KP : KC;
    const float* src = (which ? patch : clean) + (size_t)img * NROW * 85;
    int tid = threadIdx.x, lane = tid & 31, w = tid >> 5;

    // --- Phase A: coarse bucket suffix-scan -> b* ---
    if (tid < 64) {
        int c = g_bcnt[seg][tid];
        bcnt[tid] = c > BCAP ? BCAP : c;
        g_bcnt[seg][tid] = 0;                  // reset for next replay
    }
    if (tid == 0) { sNin = 0; sNtie = 0; sAllin = 0; sT = 0; sNeed = 0; sBstar = -1; sKp = 0; }
    if (tid < 80) ccnt[tid] = 0;
    if (tid < 256) hfine[tid] = 0;
    __syncthreads();
    if (tid < 64) {
        int val = bcnt[63 - tid];              // descending conf order
        int inc = val;
        #pragma unroll
        for (int off = 1; off < 32; off <<= 1) {
            int n = __shfl_up_sync(FULL, inc, off);
            if (lane >= off) inc += n;
        }
        if (lane == 31) wsum[w] = inc;
        __syncthreads();
        if (w == 1) inc += wsum[0];
        int total = wsum[0] + wsum[1] - (tid == 63 ? 0 : 0); // wsum[1] holds warp1 total after add? no:
        // recompute total safely below via thread 63
        int excl = inc - val;
        if (tid == 63) { if (inc <= K) sAllin = 1; }
        __syncthreads();
        if (!sAllin && excl < K && inc >= K) {  // unique crossing thread
            sBstar = 63 - tid;
            sKp = K - excl;                     // items needed from bucket b*
        }
        (void)total;
    } else {
        __syncthreads();
        __syncthreads();
    }
    __syncthreads();
    int allin = sAllin, bstar = sBstar, Kp = sKp;

    if (!allin) {
        // --- Phase A2: fine histogram of bucket b* (256 bins) ---
        int nb = bcnt[bstar];
        for (int i = tid; i < nb; i += 1024) {
            unsigned long long key = g_bucket[seg][bstar][i];
            atomicAdd(&hfine[binof(conf_of(key)) & 255], 1);
        }
        __syncthreads();
        if (tid < 256) {
            int val = hfine[255 - tid];
            int inc = val;
            #pragma unroll
            for (int off = 1; off < 32; off <<= 1) {
                int n = __shfl_up_sync(FULL, inc, off);
                if (lane >= off) inc += n;
            }
            if (lane == 31) wsum[w] = inc;
            __syncthreads();
            if (w > 0) {
                int add = 0;
                #pragma unroll
                for (int i = 0; i < 8; i++) if (i < w) add += wsum[i];
                inc += add;
            }
            int excl = inc - val;
            if (excl < Kp && inc >= Kp) {       // unique crossing thread
                sT = (bstar << 8) | (255 - tid);
                sNeed = Kp - excl;
            }
        } else {
            __syncthreads();
        }
        __syncthreads();
    }
    int T = sT, need = sNeed;

    // --- Phase B: gather candidates from buckets >= b* ---
    int blo = allin ? 0 : bstar;
    for (int b = 63; b >= blo; b--) {
        int n = bcnt[b];
        bool full_in = allin || (b > bstar);
        for (int it = 0; it < n; it += 1024) {
            int i = it + tid;
            bool v = (i < n);
            unsigned long long key = v ? g_bucket[seg][b][i] : 0ull;
            bool take_in, take_tie;
            if (full_in) { take_in = v; take_tie = false; }
            else {
                int bin = v ? binof(conf_of(key)) : 0;
                take_in  = v && (bin > T);
                take_tie = v && (bin == T);
            }
            unsigned m1 = __ballot_sync(FULL, take_in);
            if (m1) {
                int leader = __ffs(m1) - 1, base = 0;
                if (lane == leader) base = atomicAdd(&sNin, __popc(m1));
                base = __shfl_sync(FULL, base, leader);
                if (take_in) U.sel.skey[base + __popc(m1 & ((1u << lane) - 1))] = key;
            }
            unsigned m2 = __ballot_sync(FULL, take_tie);
            if (m2) {
                int leader = __ffs(m2) - 1, base = 0;
                if (lane == leader) base = atomicAdd(&sNtie, __popc(m2));
                base = __shfl_sync(FULL, base, leader);
                int p = base + __popc(m2 & ((1u << lane) - 1));
                if (take_tie) U.sel.tie[p] = key;
            }
        }
    }
    __syncthreads();
    int nin = sNin;
    int S;
    if (!allin && need > 0) {
        int nt = sNtie;
        int P = 2; while (P < nt) P <<= 1;
        for (int i = tid; i < P; i += 1024) if (i >= nt) U.sel.tie[i] = 0ull;
        __syncthreads();
        for (int k = 2; k <= P; k <<= 1)
            for (int j = k >> 1; j; j >>= 1) {
                for (int e = tid; e < P; e += 1024) {
                    int p = e ^ j;
                    if (p > e) {
                        unsigned long long a = U.sel.tie[e], b2 = U.sel.tie[p];
                        bool dsc = ((e & k) == 0);
                        if ((a < b2) == dsc) { U.sel.tie[e] = b2; U.sel.tie[p] = a; }
                    }
                }
                __syncthreads();
            }
        for (int t2 = tid; t2 < need; t2 += 1024) U.sel.skey[nin + t2] = U.sel.tie[t2];
        S = nin + need;
    } else {
        S = nin;
    }
    __syncthreads();

    // --- Phase C: decode + class grouping ---
    if (tid < S) {
        unsigned long long key = U.sel.skey[tid];
        unsigned lo32 = (unsigned)key;
        int cls = (int)(lo32 & 127u);
        int idx = 32767 - (int)((lo32 >> 7) & 32767u);
        const float* rp = src + (size_t)idx * 85;
        float cx = rp[0], cy = rp[1], ww2 = rp[2], hh2 = rp[3];
        float hw = __fmul_rn(ww2, 0.5f), hh = __fmul_rn(hh2, 0.5f);
        float4 pb, ob;
        pb.x = __fsub_rn(cx, hw); pb.y = __fsub_rn(cy, hh);
        pb.z = __fadd_rn(cx, hw); pb.w = __fadd_rn(cy, hh);
        float off = (float)cls * 4096.0f;
        ob.x = __fadd_rn(pb.x, off); ob.y = __fadd_rn(pb.y, off);
        ob.z = __fadd_rn(pb.z, off); ob.w = __fadd_rn(pb.w, off);
        g_box[which][img][tid] = pb;
        g_cls[which][img][tid] = (unsigned char)cls;
        U.sel.obox[tid] = ob;
        keepc[tid] = 1;
        int p = atomicAdd(&ccnt[cls], 1);
        if (p < 64) U.sel.clslist[cls * 64 + p] = (short)tid;
        else        g_keep[which][img][tid] = 1;   // overflow: treat as kept
    }
    for (int i = S + tid; i < K; i += 1024) g_keep[which][img][i] = 0;
    __syncthreads();

    // --- Phase D: per-class NMS, one warp per class ---
    for (int c = w; c < 80; c += 32) {
        int m = ccnt[c]; if (m > 64) m = 64;
        int base2 = c * 64;
        if (m == 0) continue;
        if (m == 1) {
            if (lane == 0) { int id = U.sel.clslist[base2]; g_keep[which][img][id] = 1; }
            continue;
        }
        if (m <= 32) {
            int id = (lane < m) ? U.sel.clslist[base2 + lane] : -1;
            unsigned long long kk = (lane < m) ? U.sel.skey[id] : 0ull;
            unsigned hi32 = (unsigned)(kk >> 32), lo32 = (unsigned)kk;
            int rank = 0;
            for (int j = 0; j < m; j++) {
                unsigned hj = __shfl_sync(FULL, hi32, j);
                unsigned lj = __shfl_sync(FULL, lo32, j);
                if (hj > hi32 || (hj == hi32 && lj > lo32)) rank++;
            }
            if (lane < m) U.sel.clslist[base2 + rank] = (short)id;
            __syncwarp();
            id = (lane < m) ? U.sel.clslist[base2 + lane] : -1;
            float4 B = (lane < m) ? U.sel.obox[id] : make_float4(0.f, 0.f, 0.f, 0.f);
            unsigned keepb = (m >= 32) ? FULL : ((1u << m) - 1u);
            for (int a = 0; a < m - 1; a++) {
                if ((keepb >> a) & 1u) {
                    float4 A;
                    A.x = __shfl_sync(FULL, B.x, a);
                    A.y = __shfl_sync(FULL, B.y, a);
                    A.z = __shfl_sync(FULL, B.z, a);
                    A.w = __shfl_sync(FULL, B.w, a);
                    bool sup = (lane > a) && (lane < m) && ((keepb >> lane) & 1u)
                               && (iou_rn(A, B) > 0.45f);
                    keepb &= ~__ballot_sync(FULL, sup);
                }
            }
            if (lane < m) g_keep[which][img][id] = (unsigned char)((keepb >> lane) & 1u);
        } else {
            if (lane == 0) {
                for (int i2 = 1; i2 < m; i2++) {
                    short v = U.sel.clslist[base2 + i2];
                    unsigned long long kv = U.sel.skey[v];
                    int j2 = i2 - 1;
                    while (j2 >= 0 && U.sel.skey[U.sel.clslist[base2 + j2]] < kv) {
                        U.sel.clslist[base2 + j2 + 1] = U.sel.clslist[base2 + j2]; j2--;
                    }
                    U.sel.clslist[base2 + j2 + 1] = v;
                }
            }
            __syncwarp();
            for (int a = 0; a < m - 1; a++) {
                int ta = U.sel.clslist[base2 + a];
                if (keepc[ta]) {
                    float4 A = U.sel.obox[ta];
                    for (int b = a + 1 + lane; b < m; b += 32) {
                        int tb = U.sel.clslist[base2 + b];
                        if (keepc[tb] && iou_rn(A, U.sel.obox[tb]) > 0.45f) keepc[tb] = 0;
                    }
                }
                __syncwarp();
            }
            for (int b = lane; b < m; b += 32) {
                int tb = U.sel.clslist[base2 + b];
                g_keep[which][img][tb] = keepc[tb];
            }
        }
    }
    __syncthreads();

    // --- Phase E: handshake + fused loss ---
    if (which == 1) {                         // patch: publish and exit
        __threadfence();
        if (tid == 0) atomicExch(&g_flag[img], 1);
        return;
    }

    int myk = 0, myc2 = 0;
    float4 myb = make_float4(0.f, 0.f, 0.f, 0.f);
    if (tid < KC) {
        myk  = g_keep[0][img][tid];
        myc2 = g_cls [0][img][tid];
        myb  = g_box [0][img][tid];
    }
    if (tid == 0) { while (atomicAdd(&g_flag[img], 0) == 0) {} }
    __syncthreads();
    if (tid < 80) ccnt[tid] = 0;
    __syncthreads();

    {
        int pk = g_keep[1][img][tid];
        int pc = g_cls [1][img][tid];
        float4 pb = g_box[1][img][tid];
        U.loss.pdiv[tid] = make_float4(__fdiv_rn(pb.x, 640.0f), __fdiv_rn(pb.y, 640.0f),
                                       __fdiv_rn(pb.z, 640.0f), __fdiv_rn(pb.w, 640.0f));
        if (pk) {
            int p = atomicAdd(&ccnt[pc], 1);
            if (p < 128) U.loss.plist[pc * 128 + p] = (short)tid;
        }
    }
    __syncthreads();

    float ss = 0.0f, nn = 0.0f;
    if (tid < KC && myk) {
        nn = 1.0f;
        float4 cd = make_float4(__fdiv_rn(myb.x, 640.0f), __fdiv_rn(myb.y, 640.0f),
                                __fdiv_rn(myb.z, 640.0f), __fdiv_rn(myb.w, 640.0f));
        float tm = 0.0f;
        int m = ccnt[myc2]; if (m > 128) m = 128;
        int base2 = myc2 * 128;
        for (int b2 = 0; b2 < m; b2++)
            tm = fmaxf(tm, iou_rn(cd, U.loss.pdiv[U.loss.plist[base2 + b2]]));
        ss = tm;
    }
    #pragma unroll
    for (int off = 16; off; off >>= 1) {
        ss += __shfl_down_sync(FULL, ss, off);
        nn += __shfl_down_sync(FULL, nn, off);
    }
    if (lane == 0) { rs[w] = ss; rn2[w] = nn; }
    __syncthreads();
    if (tid == 0) {
        float Sm = 0.0f, Nm = 0.0f;
        #pragma unroll
        for (int i = 0; i < 32; i++) { Sm += rs[i]; Nm += rn2[i]; }
        g_s[img] = Sm; g_n[img] = Nm;
        __threadfence();
        int old = atomicAdd(&g_cnt, 1);
        if (old == BIMG - 1) {
            float tot = 0.0f, cnt = 0.0f;
            for (int i = 0; i < BIMG; i++) { tot += g_s[i]; cnt += g_n[i]; }
            out[0] = (cnt > 0.0f) ? __fsub_rn(1.0f, __fdiv_rn(tot, fmaxf(cnt, 1.0f)))
                                  : 1.0f;
            g_cnt = 0;
        }
        g_flag[img] = 0;                       // reset for next replay
    }
}

// ---------------- launch ----------------------------------------------------
extern "C" void kernel_launch(void* const* d_in, const int* in_sizes, int n_in,
                              void* d_out, int out_size) {
    const float* clean = (const float*)d_in[0];
    const float* patch = (const float*)d_in[1];

    dim3 sgrid(NTILE, 16);                     // 225 x 16 tiles
    k_score<<<sgrid, 128>>>(clean, patch);
    k_select<<<16, 1024>>>(clean, patch, (float*)d_out);
}

// round 7
// speedup vs baseline: 1.6331x; 1.6331x over previous
#include <cuda_runtime.h>

#define FULL 0xFFFFFFFFu
static const int NROW = 25200;
static const int BIMG = 8;
static const int NBIN = 2048;
static const int KC   = 512;
static const int KP   = 1024;
static const int TILE = 112;               // 25200 = 225 * 112
static const int NTILE = NROW / TILE;      // 225

// ---------------- global scratch (static __device__, no allocation) -------
__device__ __align__(16) unsigned long long g_keys[2][BIMG][NROW];
__device__ int            g_hist[16][NBIN];
__device__ float4         g_box [2][BIMG][KP];
__device__ unsigned char  g_cls [2][BIMG][KP];
__device__ unsigned char  g_keep[2][BIMG][KP];
__device__ int            g_flag[BIMG];    // patch segment done flags
__device__ float          g_s[BIMG], g_n[BIMG];
__device__ int            g_cnt;

__device__ __forceinline__ float iou_rn(float4 a, float4 b) {
    float tlx = fmaxf(a.x, b.x), tly = fmaxf(a.y, b.y);
    float brx = fminf(a.z, b.z), bry = fminf(a.w, b.w);
    float w = fmaxf(__fsub_rn(brx, tlx), 0.0f);
    float h = fmaxf(__fsub_rn(bry, tly), 0.0f);
    float inter = __fmul_rn(w, h);
    float aa = __fmul_rn(__fsub_rn(a.z, a.x), __fsub_rn(a.w, a.y));
    float ab = __fmul_rn(__fsub_rn(b.z, b.x), __fsub_rn(b.w, b.y));
    float uni = __fsub_rn(__fadd_rn(aa, ab), inter);
    uni = (uni > 0.0f) ? uni : 1.0f;
    return __fdiv_rn(inter, uni);
}

__device__ __forceinline__ int binof(float conf) {
    int b = (int)(__fmul_rn(conf, 2048.0f));
    return b > NBIN - 1 ? NBIN - 1 : (b < 0 ? 0 : b);
}

// biased high-word of the smallest positive float whose bin >= B (exact).
__device__ __forceinline__ unsigned cut_for(int B) {
    if (B <= 0) return 0x80000001u;              // any valid (conf > 0) key
    if (B > NBIN - 1) return 0xFFFFFFFFu;        // nothing
    float g = (float)B / 2048.0f;                // exact; binof(g) == B
    for (;;) {                                    // climb down over round-ups
        float p = __int_as_float(__float_as_int(g) - 1);
        if ((int)(__fmul_rn(p, 2048.0f)) >= B) g = p; else break;
    }
    return __float_as_uint(g) ^ 0x80000000u;
}

// ---------------- K1: tile-staged score / key / histogram ------------------
__global__ void __launch_bounds__(128) k_score(const float* __restrict__ clean,
                                               const float* __restrict__ patch) {
    __shared__ float sd[TILE * 85];
    int seg   = blockIdx.y;
    int which = seg >> 3, img = seg & 7;
    int tile  = blockIdx.x;
    const float* base = (which ? patch : clean)
                      + ((size_t)img * NROW + (size_t)tile * TILE) * 85;
    const float4* b4 = (const float4*)base;
    float4* s4 = (float4*)sd;
    const int NV4 = TILE * 85 / 4;                      // 2380
    #pragma unroll 5
    for (int i = threadIdx.x; i < NV4; i += 128) s4[i] = b4[i];
    __syncthreads();

    int tid = threadIdx.x;
    if (tid < TILE) {
        const float* row = sd + tid * 85;
        float obj = row[4];
        float bv = -1.0f; int bc = 5;
        #pragma unroll 16
        for (int c = 5; c < 85; c++) {
            float x = __fmul_rn(row[c], obj);
            if (x > bv) { bv = x; bc = c; }             // strict > keeps earliest
        }
        int r = tile * TILE + tid;
        float TH = which ? 0.001f : 0.25f;
        unsigned long long key = 0ull;
        if (obj > TH && bv > TH) {
            unsigned u = __float_as_uint(bv) ^ 0x80000000u;
            key = ((unsigned long long)u << 32)
                | ((unsigned)(32767 - r) << 7) | (unsigned)(bc - 5);
            atomicAdd(&g_hist[seg][binof(bv)], 1);
        }
        g_keys[which][img][r] = key;                    // coalesced
    }
}

// ---------------- K2: threshold + gather + tie + NMS + fused loss ----------
__global__ void __launch_bounds__(1024) k_select(const float* __restrict__ clean,
                                                 const float* __restrict__ patch,
                                                 float* __restrict__ out) {
    __shared__ union {
        struct {
            unsigned long long skey[KP];
            unsigned long long tie[512];
            float4 obox[KP];
            short  clslist[80 * 64];
        } sel;
        struct {
            float4 pdiv[KP];
            short  plist[80 * 128];
        } loss;
    } U;
    __shared__ unsigned char keepc[KP];
    __shared__ int   ccnt[80];
    __shared__ int   wsum[32];
    __shared__ float rs[32], rn2[32];
    __shared__ int   sT, sNeed, sAllin, sNin, sNtie;
    __shared__ unsigned sCutIn, sCutTie;

    int seg = blockIdx.x;
    int which = seg >> 3, img = seg & 7;
    int K = which ? KP : KC;
    const float* src = (which ? patch : clean) + (size_t)img * NROW * 85;
    const unsigned long long* keys = g_keys[which][img];
    int tid = threadIdx.x, lane = tid & 31, w = tid >> 5;

    // --- Phase A: threshold from histogram (descending-bin chunks) ---
    const int CH = NBIN / 1024;                  // 2
    int hi = NBIN - CH * tid, lo = hi - CH;
    int s = g_hist[seg][lo] + g_hist[seg][lo + 1];
    int inc = s;
    #pragma unroll
    for (int off = 1; off < 32; off <<= 1) {
        int n = __shfl_up_sync(FULL, inc, off);
        if (lane >= off) inc += n;
    }
    if (lane == 31) wsum[w] = inc;
    if (tid == 0) { sNin = 0; sNtie = 0; sT = 0; sNeed = 0; }
    if (tid < 80) ccnt[tid] = 0;
    __syncthreads();
    if (w == 0) {
        int v = wsum[lane];
        #pragma unroll
        for (int off = 1; off < 32; off <<= 1) {
            int n = __shfl_up_sync(FULL, v, off);
            if (lane >= off) v += n;
        }
        wsum[lane] = v;
    }
    __syncthreads();
    int wbase = w ? wsum[w - 1] : 0;
    int incl = wbase + inc, excl = incl - s;
    int total = wsum[31];
    if (tid == 0) sAllin = (total <= K);
    if (total > K && excl < K && incl >= K) {     // unique crossing thread
        int acc = excl, tb = lo, hv = 0;
        for (int b = hi - 1; b >= lo; b--) {
            hv = g_hist[seg][b]; acc += hv;
            if (acc >= K) { tb = b; break; }
        }
        sT = tb;
        sNeed = K - (acc - hv);
    }
    __syncthreads();
    int T = sT, allin = sAllin, need = sNeed;

    if (tid == 0) {
        if (allin) { sCutIn = 0x80000001u; sCutTie = 0x80000001u; }
        else       { sCutIn = cut_for(T + 1); sCutTie = cut_for(T); }
    }
    for (int i = tid; i < NBIN; i += 1024) g_hist[seg][i] = 0;   // next replay
    __syncthreads();
    unsigned cutIn = sCutIn, cutTie = sCutTie;
    if (allin) cutTie = cutIn;                    // tie set empty

    // --- Phase B: vectorized gather (integer compares, 2 keys/thread/iter) ---
    const ulonglong2* keys2 = (const ulonglong2*)keys;
    const int NP = NROW / 2;                      // 12600
    const unsigned lmlt = (1u << lane) - 1u;
    for (int it = 0; it < (NP + 1023) / 1024; it++) {
        int i = it * 1024 + tid;
        ulonglong2 kk;
        if (i < NP) kk = keys2[i]; else { kk.x = 0ull; kk.y = 0ull; }
        unsigned ha = (unsigned)(kk.x >> 32), hb = (unsigned)(kk.y >> 32);
        bool ina = ha >= cutIn, inb = hb >= cutIn;
        bool ta = !ina && (ha >= cutTie), tb = !inb && (hb >= cutTie);
        unsigned ma = __ballot_sync(FULL, ina);
        unsigned mb = __ballot_sync(FULL, inb);
        int tot = __popc(ma) + __popc(mb);
        if (tot) {
            int leader = __ffs(ma | mb) - 1;
            int base = 0;
            if (lane == leader) base = atomicAdd(&sNin, tot);
            base = __shfl_sync(FULL, base, leader);
            if (ina) U.sel.skey[base + __popc(ma & lmlt)] = kk.x;
            if (inb) U.sel.skey[base + __popc(ma) + __popc(mb & lmlt)] = kk.y;
        }
        if (ta) { int p = atomicAdd(&sNtie, 1); if (p < 512) U.sel.tie[p] = kk.x; }
        if (tb) { int p = atomicAdd(&sNtie, 1); if (p < 512) U.sel.tie[p] = kk.y; }
    }
    __syncthreads();
    int nin = sNin;
    int S;
    if (!allin && need > 0) {
        int nt = sNtie; if (nt > 512) nt = 512;
        int P = 2; while (P < nt) P <<= 1;
        for (int i = tid; i < P; i += 1024) if (i >= nt) U.sel.tie[i] = 0ull;
        __syncthreads();
        for (int k = 2; k <= P; k <<= 1)
            for (int j = k >> 1; j; j >>= 1) {
                for (int e = tid; e < P; e += 1024) {
                    int p = e ^ j;
                    if (p > e) {
                        unsigned long long a = U.sel.tie[e], b2 = U.sel.tie[p];
                        bool dsc = ((e & k) == 0);
                        if ((a < b2) == dsc) { U.sel.tie[e] = b2; U.sel.tie[p] = a; }
                    }
                }
                __syncthreads();
            }
        for (int t2 = tid; t2 < need; t2 += 1024) U.sel.skey[nin + t2] = U.sel.tie[t2];
        S = nin + need;
    } else {
        S = nin;
    }
    __syncthreads();

    // --- Phase C: decode + class grouping ---
    if (tid < S) {
        unsigned long long key = U.sel.skey[tid];
        unsigned lo32 = (unsigned)key;
        int cls = (int)(lo32 & 127u);
        int idx = 32767 - (int)((lo32 >> 7) & 32767u);
        const float* rp = src + (size_t)idx * 85;
        float cx = rp[0], cy = rp[1], ww2 = rp[2], hh2 = rp[3];
        float hw = __fmul_rn(ww2, 0.5f), hh = __fmul_rn(hh2, 0.5f);
        float4 pb, ob;
        pb.x = __fsub_rn(cx, hw); pb.y = __fsub_rn(cy, hh);
        pb.z = __fadd_rn(cx, hw); pb.w = __fadd_rn(cy, hh);
        float off = (float)cls * 4096.0f;
        ob.x = __fadd_rn(pb.x, off); ob.y = __fadd_rn(pb.y, off);
        ob.z = __fadd_rn(pb.z, off); ob.w = __fadd_rn(pb.w, off);
        g_box[which][img][tid] = pb;
        g_cls[which][img][tid] = (unsigned char)cls;
        U.sel.obox[tid] = ob;
        keepc[tid] = 1;
        int p = atomicAdd(&ccnt[cls], 1);
        if (p < 64) U.sel.clslist[cls * 64 + p] = (short)tid;
        else        g_keep[which][img][tid] = 1;   // overflow: treat as kept
    }
    for (int i = S + tid; i < K; i += 1024) g_keep[which][img][i] = 0;
    __syncthreads();

    // --- Phase D: per-class NMS, one warp per class ---
    for (int c = w; c < 80; c += 32) {
        int m = ccnt[c]; if (m > 64) m = 64;
        int base2 = c * 64;
        if (m == 0) continue;
        if (m == 1) {
            if (lane == 0) { int id = U.sel.clslist[base2]; g_keep[which][img][id] = 1; }
            continue;
        }
        if (m <= 32) {
            int id = (lane < m) ? U.sel.clslist[base2 + lane] : -1;
            unsigned long long kk = (lane < m) ? U.sel.skey[id] : 0ull;
            unsigned hi32 = (unsigned)(kk >> 32), lo32 = (unsigned)kk;
            int rank = 0;
            for (int j = 0; j < m; j++) {
                unsigned hj = __shfl_sync(FULL, hi32, j);
                unsigned lj = __shfl_sync(FULL, lo32, j);
                if (hj > hi32 || (hj == hi32 && lj > lo32)) rank++;
            }
            if (lane < m) U.sel.clslist[base2 + rank] = (short)id;
            __syncwarp();
            id = (lane < m) ? U.sel.clslist[base2 + lane] : -1;
            float4 B = (lane < m) ? U.sel.obox[id] : make_float4(0.f, 0.f, 0.f, 0.f);
            unsigned keepb = (m >= 32) ? FULL : ((1u << m) - 1u);
            for (int a = 0; a < m - 1; a++) {
                if ((keepb >> a) & 1u) {
                    float4 A;
                    A.x = __shfl_sync(FULL, B.x, a);
                    A.y = __shfl_sync(FULL, B.y, a);
                    A.z = __shfl_sync(FULL, B.z, a);
                    A.w = __shfl_sync(FULL, B.w, a);
                    bool sup = (lane > a) && (lane < m) && ((keepb >> lane) & 1u)
                               && (iou_rn(A, B) > 0.45f);
                    keepb &= ~__ballot_sync(FULL, sup);
                }
            }
            if (lane < m) g_keep[which][img][id] = (unsigned char)((keepb >> lane) & 1u);
        } else {
            if (lane == 0) {
                for (int i2 = 1; i2 < m; i2++) {
                    short v = U.sel.clslist[base2 + i2];
                    unsigned long long kv = U.sel.skey[v];
                    int j2 = i2 - 1;
                    while (j2 >= 0 && U.sel.skey[U.sel.clslist[base2 + j2]] < kv) {
                        U.sel.clslist[base2 + j2 + 1] = U.sel.clslist[base2 + j2]; j2--;
                    }
                    U.sel.clslist[base2 + j2 + 1] = v;
                }
            }
            __syncwarp();
            for (int a = 0; a < m - 1; a++) {
                int ta = U.sel.clslist[base2 + a];
                if (keepc[ta]) {
                    float4 A = U.sel.obox[ta];
                    for (int b = a + 1 + lane; b < m; b += 32) {
                        int tb = U.sel.clslist[base2 + b];
                        if (keepc[tb] && iou_rn(A, U.sel.obox[tb]) > 0.45f) keepc[tb] = 0;
                    }
                }
                __syncwarp();
            }
            for (int b = lane; b < m; b += 32) {
                int tb = U.sel.clslist[base2 + b];
                g_keep[which][img][tb] = keepc[tb];
            }
        }
    }
    __syncthreads();

    // --- Phase E: handshake + fused loss ---
    if (which == 1) {                         // patch: publish and exit
        __threadfence();
        if (tid == 0) atomicExch(&g_flag[img], 1);
        return;
    }

    int myk = 0, myc2 = 0;
    float4 myb = make_float4(0.f, 0.f, 0.f, 0.f);
    if (tid < KC) {
        myk  = g_keep[0][img][tid];
        myc2 = g_cls [0][img][tid];
        myb  = g_box [0][img][tid];
    }
    if (tid == 0) { while (atomicAdd(&g_flag[img], 0) == 0) {} }
    __syncthreads();                          // flag seen -> patch data visible
    if (tid < 80) ccnt[tid] = 0;
    __syncthreads();

    {
        int pk = g_keep[1][img][tid];
        int pc = g_cls [1][img][tid];
        float4 pb = g_box[1][img][tid];
        U.loss.pdiv[tid] = make_float4(__fdiv_rn(pb.x, 640.0f), __fdiv_rn(pb.y, 640.0f),
                                       __fdiv_rn(pb.z, 640.0f), __fdiv_rn(pb.w, 640.0f));
        if (pk) {
            int p = atomicAdd(&ccnt[pc], 1);
            if (p < 128) U.loss.plist[pc * 128 + p] = (short)tid;
        }
    }
    __syncthreads();

    float ss = 0.0f, nn = 0.0f;
    if (tid < KC && myk) {
        nn = 1.0f;
        float4 cd = make_float4(__fdiv_rn(myb.x, 640.0f), __fdiv_rn(myb.y, 640.0f),
                                __fdiv_rn(myb.z, 640.0f), __fdiv_rn(myb.w, 640.0f));
        float tm = 0.0f;
        int m = ccnt[myc2]; if (m > 128) m = 128;
        int base2 = myc2 * 128;
        for (int b2 = 0; b2 < m; b2++)
            tm = fmaxf(tm, iou_rn(cd, U.loss.pdiv[U.loss.plist[base2 + b2]]));
        ss = tm;
    }
    #pragma unroll
    for (int off = 16; off; off >>= 1) {
        ss += __shfl_down_sync(FULL, ss, off);
        nn += __shfl_down_sync(FULL, nn, off);
    }
    if (lane == 0) { rs[w] = ss; rn2[w] = nn; }
    __syncthreads();
    if (tid == 0) {
        float Sm = 0.0f, Nm = 0.0f;
        #pragma unroll
        for (int i = 0; i < 32; i++) { Sm += rs[i]; Nm += rn2[i]; }
        g_s[img] = Sm; g_n[img] = Nm;
        __threadfence();
        int old = atomicAdd(&g_cnt, 1);
        if (old == BIMG - 1) {
            float tot = 0.0f, cnt = 0.0f;
            for (int i = 0; i < BIMG; i++) { tot += g_s[i]; cnt += g_n[i]; }
            out[0] = (cnt > 0.0f) ? __fsub_rn(1.0f, __fdiv_rn(tot, fmaxf(cnt, 1.0f)))
                                  : 1.0f;
            g_cnt = 0;
        }
        g_flag[img] = 0;                       // reset for next replay
    }
}

// ---------------- launch ----------------------------------------------------
extern "C" void kernel_launch(void* const* d_in, const int* in_sizes, int n_in,
                              void* d_out, int out_size) {
    const float* clean = (const float*)d_in[0];
    const float* patch = (const float*)d_in[1];

    dim3 sgrid(NTILE, 16);                     // 225 x 16 tiles
    k_score<<<sgrid, 128>>>(clean, patch);
    k_select<<<16, 1024>>>(clean, patch, (float*)d_out);
}